// round 6
// baseline (speedup 1.0000x reference)
#include <cuda_runtime.h>

// E=500000, P=4000000, D=U=64.
__device__ int g_counts[500032];      // per-dst neighbor count
__device__ int g_offsets[500032];     // exclusive prefix of counts
__device__ int g_rank[4000000];       // per-pair rank within its dst
__device__ int g_src_sorted[4000000]; // src ids grouped by dst
__device__ int g_blockSums[512];
__device__ int g_blockOffs[512];

// f32x2 helpers (sm_103a packed fp32 pipe, PTX-only)
#define FMA2(d, a, b) \
    asm("fma.rn.f32x2 %0, %1, %2, %0;" : "+l"(d) : "l"(a), "l"(b))
#define PACK2(p, x) \
    asm("mov.b64 %0, {%1, %1};" : "=l"(p) : "f"(x))
#define UNPACK2(lo, hi, p) \
    asm("mov.b64 {%0, %1}, %2;" : "=f"(lo), "=f"(hi) : "l"(p))

// ---------------------------------------------------------------------------
__global__ void zero_counts_kernel(int E)
{
    int i = blockIdx.x * 256 + threadIdx.x;
    if (i < E) g_counts[i] = 0;
}

// Histogram + rank capture: the atomicAdd return IS the pair's final slot
// within its dst group, so the scatter pass needs no atomics at all.
__global__ void hist_kernel(const int4* __restrict__ nbr2, int P2, int P)
{
    int q = blockIdx.x * 256 + threadIdx.x;
    if (q >= P2) return;
    int4 e = __ldcs(&nbr2[q]);         // {dst0, src0, dst1, src1}
    int r0 = atomicAdd(&g_counts[e.x], 1);
    __stcs(&g_rank[q * 2], r0);
    int p1 = q * 2 + 1;
    if (p1 < P) {
        int r1 = atomicAdd(&g_counts[e.z], 1);
        __stcs(&g_rank[p1], r1);
    }
}

__global__ void scan_partial_kernel(int E)
{
    __shared__ int s[256];
    const int tid  = threadIdx.x;
    const int base = blockIdx.x * 1024 + tid * 4;
    int t = 0;
    #pragma unroll
    for (int j = 0; j < 4; j++) {
        int idx = base + j;
        if (idx < E) t += g_counts[idx];
    }
    s[tid] = t;
    __syncthreads();
    for (int o = 128; o > 0; o >>= 1) {
        if (tid < o) s[tid] += s[tid + o];
        __syncthreads();
    }
    if (tid == 0) g_blockSums[blockIdx.x] = s[0];
}

__global__ void scan_blocksums_kernel(int NB)
{
    __shared__ int s[512];
    const int tid = threadIdx.x;
    int v = (tid < NB) ? g_blockSums[tid] : 0;
    s[tid] = v;
    __syncthreads();
    for (int o = 1; o < 512; o <<= 1) {
        int t = (tid >= o) ? s[tid - o] : 0;
        __syncthreads();
        s[tid] += t;
        __syncthreads();
    }
    if (tid < NB) g_blockOffs[tid] = s[tid] - v;
}

__global__ void scan_final_kernel(int E)
{
    __shared__ int s[256];
    const int tid  = threadIdx.x;
    const int base = blockIdx.x * 1024 + tid * 4;

    int c[4];
    int tsum = 0;
    #pragma unroll
    for (int j = 0; j < 4; j++) {
        int idx = base + j;
        c[j] = (idx < E) ? g_counts[idx] : 0;
        tsum += c[j];
    }
    s[tid] = tsum;
    __syncthreads();
    for (int o = 1; o < 256; o <<= 1) {
        int t = (tid >= o) ? s[tid - o] : 0;
        __syncthreads();
        s[tid] += t;
        __syncthreads();
    }
    int run = g_blockOffs[blockIdx.x] + (s[tid] - tsum);
    #pragma unroll
    for (int j = 0; j < 4; j++) {
        int idx = base + j;
        if (idx < E) g_offsets[idx] = run;
        run += c[j];
    }
}

// Atomic-free scatter: position = offsets[dst] + saved rank.
__global__ void sort_scatter_kernel(const int4* __restrict__ nbr2, int P2, int P)
{
    int q = blockIdx.x * 256 + threadIdx.x;
    if (q >= P2) return;
    int4 e = __ldcs(&nbr2[q]);
    int2 rk = __ldcs(reinterpret_cast<const int2*>(&g_rank[q * 2]));
    __stcs(&g_src_sorted[g_offsets[e.x] + rk.x], e.y);
    int p1 = q * 2 + 1;
    if (p1 < P)
        __stcs(&g_src_sorted[g_offsets[e.z] + rk.y], e.w);
}

// ---------------------------------------------------------------------------
// Fused aggregate + GEMM.
// Phase 1: half-warp team per dst row, MLP-8 gather. L2 policy: feat is the
// ONLY reusable data (128 MB ~ L2-sized), so the one-shot streams (sorted
// src ids in, out tile stores) use evict-first (__ldcs/__stcs) to keep the
// feat table resident.
// Phase 2: 64x64 f32x2 GEMM + bias.
// ---------------------------------------------------------------------------
__global__ void __launch_bounds__(256) agg_gemm_kernel(
    const float* __restrict__ feat,   // [E, 64]
    const float* __restrict__ W,      // [64, 64]
    const float* __restrict__ bias,   // [64]
    float* __restrict__ out,          // [E, 64]
    int E)
{
    __shared__ float sW[64 * 64];     // sW[k*64 + u]
    __shared__ float sA[64 * 66];     // sA[k*66 + r] (transposed, pad 66)

    const int tid  = threadIdx.x;
    const int row0 = blockIdx.x * 64;

    #pragma unroll
    for (int i = tid; i < 64 * 64; i += 256)
        sW[i] = W[i];

    // ---- Phase 1: gather + register accumulation -------------------------
    const int lane16 = tid & 15;          // column segment (16B)
    const int tteam  = tid >> 4;          // 0..15
    const float* __restrict__ fb = feat + lane16 * 4;

    #pragma unroll
    for (int rr = 0; rr < 4; rr++) {
        const int lr = rr * 16 + tteam;   // local row 0..63
        const int r  = row0 + lr;

        float a0 = 0.f, a1 = 0.f, a2 = 0.f, a3 = 0.f;
        if (r < E) {
            const int start = g_offsets[r];
            const int cnt   = g_counts[r];
            int i = 0;
            for (; i + 8 <= cnt; i += 8) {
                int s[8];
                #pragma unroll
                for (int j = 0; j < 8; j++)
                    s[j] = __ldcs(&g_src_sorted[start + i + j]);
                float4 v[8];
                #pragma unroll
                for (int j = 0; j < 8; j++)
                    v[j] = *reinterpret_cast<const float4*>(fb + (long)s[j] * 64);
                #pragma unroll
                for (int j = 0; j < 8; j++) {
                    a0 += v[j].x; a1 += v[j].y; a2 += v[j].z; a3 += v[j].w;
                }
            }
            for (; i < cnt; i++) {
                int s = __ldcs(&g_src_sorted[start + i]);
                float4 v = *reinterpret_cast<const float4*>(fb + (long)s * 64);
                a0 += v.x; a1 += v.y; a2 += v.z; a3 += v.w;
            }
        }
        sA[(lane16 * 4 + 0) * 66 + lr] = a0;
        sA[(lane16 * 4 + 1) * 66 + lr] = a1;
        sA[(lane16 * 4 + 2) * 66 + lr] = a2;
        sA[(lane16 * 4 + 3) * 66 + lr] = a3;
    }
    __syncthreads();

    // ---- Phase 2: 64x64 GEMM (f32x2), bias, store ------------------------
    const int rt = tid >> 4;
    const int ct = tid & 15;

    unsigned long long accq[2][4];
    #pragma unroll
    for (int rp = 0; rp < 2; rp++)
        #pragma unroll
        for (int j = 0; j < 4; j++)
            accq[rp][j] = 0ULL;

    #pragma unroll
    for (int k = 0; k < 64; k++) {
        const unsigned long long a01 =
            *reinterpret_cast<const unsigned long long*>(&sA[k * 66 + rt * 4]);
        const unsigned long long a23 =
            *reinterpret_cast<const unsigned long long*>(&sA[k * 66 + rt * 4 + 2]);
        const float4 w = *reinterpret_cast<const float4*>(&sW[k * 64 + ct * 4]);

        unsigned long long wx, wy, wz, ww;
        PACK2(wx, w.x); PACK2(wy, w.y); PACK2(wz, w.z); PACK2(ww, w.w);

        FMA2(accq[0][0], a01, wx); FMA2(accq[0][1], a01, wy);
        FMA2(accq[0][2], a01, wz); FMA2(accq[0][3], a01, ww);
        FMA2(accq[1][0], a23, wx); FMA2(accq[1][1], a23, wy);
        FMA2(accq[1][2], a23, wz); FMA2(accq[1][3], a23, ww);
    }

    float res[4][4];
    #pragma unroll
    for (int rp = 0; rp < 2; rp++)
        #pragma unroll
        for (int j = 0; j < 4; j++) {
            float lo, hi;
            UNPACK2(lo, hi, accq[rp][j]);
            res[rp * 2 + 0][j] = lo;
            res[rp * 2 + 1][j] = hi;
        }

    const float4 b = *reinterpret_cast<const float4*>(&bias[ct * 4]);

    #pragma unroll
    for (int i = 0; i < 4; i++) {
        int row = row0 + rt * 4 + i;
        if (row < E) {
            float4 v;
            v.x = res[i][0] + b.x;
            v.y = res[i][1] + b.y;
            v.z = res[i][2] + b.z;
            v.w = res[i][3] + b.w;
            __stcs(reinterpret_cast<float4*>(&out[row * 64 + ct * 4]), v);
        }
    }
}

// ---------------------------------------------------------------------------
extern "C" void kernel_launch(void* const* d_in, const int* in_sizes, int n_in,
                              void* d_out, int out_size)
{
    const float* feat = (const float*)d_in[0];   // [E, 64] f32
    const int*   nbr  = (const int*)d_in[1];     // [P, 2]  i32
    const float* W    = (const float*)d_in[2];   // [64, 64] f32
    const float* bias = (const float*)d_in[3];   // [64] f32
    float* out = (float*)d_out;                  // [E, 64] f32

    const int E = in_sizes[0] / 64;
    const int P = in_sizes[1] / 2;

    const int blkE  = (E + 255) / 256;
    const int P2    = (P + 1) / 2;
    const int blkP2 = (P2 + 255) / 256;
    const int NB    = (E + 1023) / 1024;         // <= 512

    zero_counts_kernel<<<blkE, 256>>>(E);
    hist_kernel<<<blkP2, 256>>>((const int4*)nbr, P2, P);
    scan_partial_kernel<<<NB, 256>>>(E);
    scan_blocksums_kernel<<<1, 512>>>(NB);
    scan_final_kernel<<<NB, 256>>>(E);
    sort_scatter_kernel<<<blkP2, 256>>>((const int4*)nbr, P2, P);

    const int blkA = (E + 63) / 64;
    agg_gemm_kernel<<<blkA, 256>>>(feat, W, bias, out, E);
}

// round 7
// speedup vs baseline: 1.0730x; 1.0730x over previous
#include <cuda_runtime.h>

// E=500000, P=4000000, D=U=64.
__device__ int g_counts[500032];      // per-dst neighbor count
__device__ int g_offsets[500032];     // exclusive prefix of counts
__device__ int g_cursor[500032];      // scatter cursors
__device__ int g_src_sorted[4000000]; // src ids grouped by dst
__device__ int g_blockSums[512];
__device__ int g_blockOffs[512];

// f32x2 helpers (sm_103a packed fp32 pipe, PTX-only)
#define FMA2(d, a, b) \
    asm("fma.rn.f32x2 %0, %1, %2, %0;" : "+l"(d) : "l"(a), "l"(b))
#define PACK2(p, x) \
    asm("mov.b64 %0, {%1, %1};" : "=l"(p) : "f"(x))
#define UNPACK2(lo, hi, p) \
    asm("mov.b64 {%0, %1}, %2;" : "=f"(lo), "=f"(hi) : "l"(p))

// ---------------------------------------------------------------------------
__global__ void hist_kernel(const int4* __restrict__ nbr2, int P2, int P)
{
    int q = blockIdx.x * 256 + threadIdx.x;
    if (q >= P2) return;
    int4 e = __ldcs(&nbr2[q]);         // {dst0, src0, dst1, src1}
    atomicAdd(&g_counts[e.x], 1);
    int p1 = q * 2 + 1;
    if (p1 < P) atomicAdd(&g_counts[e.z], 1);
}

__global__ void scan_partial_kernel(int E)
{
    __shared__ int s[256];
    const int tid  = threadIdx.x;
    const int base = blockIdx.x * 1024 + tid * 4;
    int t = 0;
    #pragma unroll
    for (int j = 0; j < 4; j++) {
        int idx = base + j;
        if (idx < E) t += g_counts[idx];
    }
    s[tid] = t;
    __syncthreads();
    for (int o = 128; o > 0; o >>= 1) {
        if (tid < o) s[tid] += s[tid + o];
        __syncthreads();
    }
    if (tid == 0) g_blockSums[blockIdx.x] = s[0];
}

__global__ void scan_blocksums_kernel(int NB)
{
    __shared__ int s[512];
    const int tid = threadIdx.x;
    int v = (tid < NB) ? g_blockSums[tid] : 0;
    s[tid] = v;
    __syncthreads();
    for (int o = 1; o < 512; o <<= 1) {
        int t = (tid >= o) ? s[tid - o] : 0;
        __syncthreads();
        s[tid] += t;
        __syncthreads();
    }
    if (tid < NB) g_blockOffs[tid] = s[tid] - v;
}

__global__ void scan_final_kernel(int E)
{
    __shared__ int s[256];
    const int tid  = threadIdx.x;
    const int base = blockIdx.x * 1024 + tid * 4;

    int c[4];
    int tsum = 0;
    #pragma unroll
    for (int j = 0; j < 4; j++) {
        int idx = base + j;
        c[j] = (idx < E) ? g_counts[idx] : 0;
        tsum += c[j];
    }
    s[tid] = tsum;
    __syncthreads();
    for (int o = 1; o < 256; o <<= 1) {
        int t = (tid >= o) ? s[tid - o] : 0;
        __syncthreads();
        s[tid] += t;
        __syncthreads();
    }
    int run = g_blockOffs[blockIdx.x] + (s[tid] - tsum);
    #pragma unroll
    for (int j = 0; j < 4; j++) {
        int idx = base + j;
        if (idx < E) {
            g_offsets[idx] = run;
            g_cursor[idx]  = run;
        }
        run += c[j];
    }
}

__global__ void sort_scatter_kernel(const int4* __restrict__ nbr2, int P2, int P)
{
    int q = blockIdx.x * 256 + threadIdx.x;
    if (q >= P2) return;
    int4 e = __ldcs(&nbr2[q]);
    int pos0 = atomicAdd(&g_cursor[e.x], 1);
    g_src_sorted[pos0] = e.y;
    int p1 = q * 2 + 1;
    if (p1 < P) {
        int pos1 = atomicAdd(&g_cursor[e.z], 1);
        g_src_sorted[pos1] = e.w;
    }
}

// ---------------------------------------------------------------------------
// Fused aggregate + GEMM.
// Phase 1: half-warp team per dst row, MLP-8 gather, with SOFTWARE-PIPELINED
// index prefetch: batch i+1's 8 indices are loaded while batch i's 8 feature
// rows are in flight, so the index L2 latency is never exposed in the
// steady state.
// Phase 2: 64x64 f32x2 GEMM + bias.
// ---------------------------------------------------------------------------
__global__ void __launch_bounds__(256) agg_gemm_kernel(
    const float* __restrict__ feat,   // [E, 64]
    const float* __restrict__ W,      // [64, 64]
    const float* __restrict__ bias,   // [64]
    float* __restrict__ out,          // [E, 64]
    int E)
{
    __shared__ float sW[64 * 64];     // sW[k*64 + u]
    __shared__ float sA[64 * 66];     // sA[k*66 + r] (transposed, pad 66)

    const int tid  = threadIdx.x;
    const int row0 = blockIdx.x * 64;

    #pragma unroll
    for (int i = tid; i < 64 * 64; i += 256)
        sW[i] = W[i];

    // ---- Phase 1: gather + register accumulation -------------------------
    const int lane16 = tid & 15;          // column segment (16B)
    const int tteam  = tid >> 4;          // 0..15
    const float* __restrict__ fb = feat + lane16 * 4;

    #pragma unroll
    for (int rr = 0; rr < 4; rr++) {
        const int lr = rr * 16 + tteam;   // local row 0..63
        const int r  = row0 + lr;

        float a0 = 0.f, a1 = 0.f, a2 = 0.f, a3 = 0.f;
        if (r < E) {
            const int start = g_offsets[r];
            const int cnt   = g_counts[r];
            int i = 0;

            if (cnt >= 8) {
                // prologue: first batch's indices
                int sc[8];
                #pragma unroll
                for (int j = 0; j < 8; j++)
                    sc[j] = g_src_sorted[start + j];

                // steady state: prefetch next indices, then load current rows
                for (; i + 16 <= cnt; i += 8) {
                    int sn[8];
                    #pragma unroll
                    for (int j = 0; j < 8; j++)
                        sn[j] = g_src_sorted[start + i + 8 + j];

                    float4 v[8];
                    #pragma unroll
                    for (int j = 0; j < 8; j++)
                        v[j] = *reinterpret_cast<const float4*>(fb + (long)sc[j] * 64);
                    #pragma unroll
                    for (int j = 0; j < 8; j++) {
                        a0 += v[j].x; a1 += v[j].y; a2 += v[j].z; a3 += v[j].w;
                    }
                    #pragma unroll
                    for (int j = 0; j < 8; j++)
                        sc[j] = sn[j];
                }

                // epilogue: last full batch
                {
                    float4 v[8];
                    #pragma unroll
                    for (int j = 0; j < 8; j++)
                        v[j] = *reinterpret_cast<const float4*>(fb + (long)sc[j] * 64);
                    #pragma unroll
                    for (int j = 0; j < 8; j++) {
                        a0 += v[j].x; a1 += v[j].y; a2 += v[j].z; a3 += v[j].w;
                    }
                    i += 8;
                }
            }

            for (; i < cnt; i++) {
                int s = g_src_sorted[start + i];
                float4 v = *reinterpret_cast<const float4*>(fb + (long)s * 64);
                a0 += v.x; a1 += v.y; a2 += v.z; a3 += v.w;
            }
        }
        sA[(lane16 * 4 + 0) * 66 + lr] = a0;
        sA[(lane16 * 4 + 1) * 66 + lr] = a1;
        sA[(lane16 * 4 + 2) * 66 + lr] = a2;
        sA[(lane16 * 4 + 3) * 66 + lr] = a3;
    }
    __syncthreads();

    // ---- Phase 2: 64x64 GEMM (f32x2), bias, store ------------------------
    const int rt = tid >> 4;
    const int ct = tid & 15;

    unsigned long long accq[2][4];
    #pragma unroll
    for (int rp = 0; rp < 2; rp++)
        #pragma unroll
        for (int j = 0; j < 4; j++)
            accq[rp][j] = 0ULL;

    #pragma unroll
    for (int k = 0; k < 64; k++) {
        const unsigned long long a01 =
            *reinterpret_cast<const unsigned long long*>(&sA[k * 66 + rt * 4]);
        const unsigned long long a23 =
            *reinterpret_cast<const unsigned long long*>(&sA[k * 66 + rt * 4 + 2]);
        const float4 w = *reinterpret_cast<const float4*>(&sW[k * 64 + ct * 4]);

        unsigned long long wx, wy, wz, ww;
        PACK2(wx, w.x); PACK2(wy, w.y); PACK2(wz, w.z); PACK2(ww, w.w);

        FMA2(accq[0][0], a01, wx); FMA2(accq[0][1], a01, wy);
        FMA2(accq[0][2], a01, wz); FMA2(accq[0][3], a01, ww);
        FMA2(accq[1][0], a23, wx); FMA2(accq[1][1], a23, wy);
        FMA2(accq[1][2], a23, wz); FMA2(accq[1][3], a23, ww);
    }

    float res[4][4];
    #pragma unroll
    for (int rp = 0; rp < 2; rp++)
        #pragma unroll
        for (int j = 0; j < 4; j++) {
            float lo, hi;
            UNPACK2(lo, hi, accq[rp][j]);
            res[rp * 2 + 0][j] = lo;
            res[rp * 2 + 1][j] = hi;
        }

    const float4 b = *reinterpret_cast<const float4*>(&bias[ct * 4]);

    #pragma unroll
    for (int i = 0; i < 4; i++) {
        int row = row0 + rt * 4 + i;
        if (row < E) {
            float4 v;
            v.x = res[i][0] + b.x;
            v.y = res[i][1] + b.y;
            v.z = res[i][2] + b.z;
            v.w = res[i][3] + b.w;
            *reinterpret_cast<float4*>(&out[row * 64 + ct * 4]) = v;
        }
    }
}

// ---------------------------------------------------------------------------
extern "C" void kernel_launch(void* const* d_in, const int* in_sizes, int n_in,
                              void* d_out, int out_size)
{
    const float* feat = (const float*)d_in[0];   // [E, 64] f32
    const int*   nbr  = (const int*)d_in[1];     // [P, 2]  i32
    const float* W    = (const float*)d_in[2];   // [64, 64] f32
    const float* bias = (const float*)d_in[3];   // [64] f32
    float* out = (float*)d_out;                  // [E, 64] f32

    const int E = in_sizes[0] / 64;
    const int P = in_sizes[1] / 2;

    const int P2    = (P + 1) / 2;
    const int blkP2 = (P2 + 255) / 256;
    const int NB    = (E + 1023) / 1024;         // <= 512

    // zero counts via async memset (graph-capturable, no alloc)
    void* counts_ptr = nullptr;
    cudaGetSymbolAddress(&counts_ptr, g_counts);
    cudaMemsetAsync(counts_ptr, 0, (size_t)E * sizeof(int), 0);

    hist_kernel<<<blkP2, 256>>>((const int4*)nbr, P2, P);
    scan_partial_kernel<<<NB, 256>>>(E);
    scan_blocksums_kernel<<<1, 512>>>(NB);
    scan_final_kernel<<<NB, 256>>>(E);
    sort_scatter_kernel<<<blkP2, 256>>>((const int4*)nbr, P2, P);

    const int blkA = (E + 63) / 64;
    agg_gemm_kernel<<<blkA, 256>>>(feat, W, bias, out, E);
}

// round 8
// speedup vs baseline: 1.0786x; 1.0052x over previous
#include <cuda_runtime.h>
#include <cuda_fp16.h>

// E=500000, P=4000000, D=U=64.
__device__ int g_counts[500032];      // per-dst neighbor count
__device__ int g_offsets[500032];     // exclusive prefix of counts
__device__ int g_cursor[500032];      // scatter cursors
__device__ int g_src_sorted[4000000]; // src ids grouped by dst
__device__ int g_blockSums[512];
__device__ int g_blockOffs[512];
__device__ __half g_feat_h[500000 * 64];  // fp16 staged feature table (64 MB)

// f32x2 helpers (sm_103a packed fp32 pipe, PTX-only)
#define FMA2(d, a, b) \
    asm("fma.rn.f32x2 %0, %1, %2, %0;" : "+l"(d) : "l"(a), "l"(b))
#define PACK2(p, x) \
    asm("mov.b64 %0, {%1, %1};" : "=l"(p) : "f"(x))
#define UNPACK2(lo, hi, p) \
    asm("mov.b64 {%0, %1}, %2;" : "=f"(lo), "=f"(hi) : "l"(p))

// ---------------------------------------------------------------------------
// Stage feat into fp16 (halves gather bytes; 64 MB table then fits L2 with
// room to spare). Pure streaming: read float4, write 4 halves (8B).
// ---------------------------------------------------------------------------
__global__ void convert_kernel(const float4* __restrict__ feat4, int n4)
{
    int i = blockIdx.x * 256 + threadIdx.x;
    if (i >= n4) return;
    float4 v = __ldcs(&feat4[i]);
    __half2 h0 = __floats2half2_rn(v.x, v.y);
    __half2 h1 = __floats2half2_rn(v.z, v.w);
    uint2 u;
    u.x = *reinterpret_cast<unsigned int*>(&h0);
    u.y = *reinterpret_cast<unsigned int*>(&h1);
    reinterpret_cast<uint2*>(g_feat_h)[i] = u;
}

// ---------------------------------------------------------------------------
__global__ void hist_kernel(const int4* __restrict__ nbr2, int P2, int P)
{
    int q = blockIdx.x * 256 + threadIdx.x;
    if (q >= P2) return;
    int4 e = __ldcs(&nbr2[q]);         // {dst0, src0, dst1, src1}
    atomicAdd(&g_counts[e.x], 1);
    int p1 = q * 2 + 1;
    if (p1 < P) atomicAdd(&g_counts[e.z], 1);
}

__global__ void scan_partial_kernel(int E)
{
    __shared__ int s[256];
    const int tid  = threadIdx.x;
    const int base = blockIdx.x * 1024 + tid * 4;
    int t = 0;
    #pragma unroll
    for (int j = 0; j < 4; j++) {
        int idx = base + j;
        if (idx < E) t += g_counts[idx];
    }
    s[tid] = t;
    __syncthreads();
    for (int o = 128; o > 0; o >>= 1) {
        if (tid < o) s[tid] += s[tid + o];
        __syncthreads();
    }
    if (tid == 0) g_blockSums[blockIdx.x] = s[0];
}

__global__ void scan_blocksums_kernel(int NB)
{
    __shared__ int s[512];
    const int tid = threadIdx.x;
    int v = (tid < NB) ? g_blockSums[tid] : 0;
    s[tid] = v;
    __syncthreads();
    for (int o = 1; o < 512; o <<= 1) {
        int t = (tid >= o) ? s[tid - o] : 0;
        __syncthreads();
        s[tid] += t;
        __syncthreads();
    }
    if (tid < NB) g_blockOffs[tid] = s[tid] - v;
}

__global__ void scan_final_kernel(int E)
{
    __shared__ int s[256];
    const int tid  = threadIdx.x;
    const int base = blockIdx.x * 1024 + tid * 4;

    int c[4];
    int tsum = 0;
    #pragma unroll
    for (int j = 0; j < 4; j++) {
        int idx = base + j;
        c[j] = (idx < E) ? g_counts[idx] : 0;
        tsum += c[j];
    }
    s[tid] = tsum;
    __syncthreads();
    for (int o = 1; o < 256; o <<= 1) {
        int t = (tid >= o) ? s[tid - o] : 0;
        __syncthreads();
        s[tid] += t;
        __syncthreads();
    }
    int run = g_blockOffs[blockIdx.x] + (s[tid] - tsum);
    #pragma unroll
    for (int j = 0; j < 4; j++) {
        int idx = base + j;
        if (idx < E) {
            g_offsets[idx] = run;
            g_cursor[idx]  = run;
        }
        run += c[j];
    }
}

__global__ void sort_scatter_kernel(const int4* __restrict__ nbr2, int P2, int P)
{
    int q = blockIdx.x * 256 + threadIdx.x;
    if (q >= P2) return;
    int4 e = __ldcs(&nbr2[q]);
    int pos0 = atomicAdd(&g_cursor[e.x], 1);
    g_src_sorted[pos0] = e.y;
    int p1 = q * 2 + 1;
    if (p1 < P) {
        int pos1 = atomicAdd(&g_cursor[e.z], 1);
        g_src_sorted[pos1] = e.w;
    }
}

// ---------------------------------------------------------------------------
// Fused aggregate + GEMM.
// Phase 1: half-warp team per dst row; each lane owns 4 columns and does one
// 8B LDG per neighbor from the fp16 table (16 lanes x 8B = 128B contiguous
// row). MLP-8 unroll (R5 structure). Accumulation in fp32.
// Phase 2: 64x64 f32x2 GEMM + bias (fp32 throughout).
// ---------------------------------------------------------------------------
__global__ void __launch_bounds__(256) agg_gemm_kernel(
    const float* __restrict__ W,      // [64, 64]
    const float* __restrict__ bias,   // [64]
    float* __restrict__ out,          // [E, 64]
    int E)
{
    __shared__ float sW[64 * 64];     // sW[k*64 + u]
    __shared__ float sA[64 * 66];     // sA[k*66 + r] (transposed, pad 66)

    const int tid  = threadIdx.x;
    const int row0 = blockIdx.x * 64;

    #pragma unroll
    for (int i = tid; i < 64 * 64; i += 256)
        sW[i] = W[i];

    // ---- Phase 1: gather + register accumulation -------------------------
    const int lane16 = tid & 15;          // column segment (4 halves = 8B)
    const int tteam  = tid >> 4;          // 0..15
    const uint2* __restrict__ fh =
        reinterpret_cast<const uint2*>(g_feat_h) + lane16;  // row stride 16

    #pragma unroll
    for (int rr = 0; rr < 4; rr++) {
        const int lr = rr * 16 + tteam;   // local row 0..63
        const int r  = row0 + lr;

        float a0 = 0.f, a1 = 0.f, a2 = 0.f, a3 = 0.f;
        if (r < E) {
            const int start = g_offsets[r];
            const int cnt   = g_counts[r];
            int i = 0;
            for (; i + 8 <= cnt; i += 8) {
                int s[8];
                #pragma unroll
                for (int j = 0; j < 8; j++)
                    s[j] = __ldcs(&g_src_sorted[start + i + j]);
                uint2 v[8];
                #pragma unroll
                for (int j = 0; j < 8; j++)
                    v[j] = fh[(long)s[j] * 16];
                #pragma unroll
                for (int j = 0; j < 8; j++) {
                    float2 f0 = __half22float2(*reinterpret_cast<__half2*>(&v[j].x));
                    float2 f1 = __half22float2(*reinterpret_cast<__half2*>(&v[j].y));
                    a0 += f0.x; a1 += f0.y; a2 += f1.x; a3 += f1.y;
                }
            }
            for (; i < cnt; i++) {
                int s = __ldcs(&g_src_sorted[start + i]);
                uint2 v = fh[(long)s * 16];
                float2 f0 = __half22float2(*reinterpret_cast<__half2*>(&v.x));
                float2 f1 = __half22float2(*reinterpret_cast<__half2*>(&v.y));
                a0 += f0.x; a1 += f0.y; a2 += f1.x; a3 += f1.y;
            }
        }
        sA[(lane16 * 4 + 0) * 66 + lr] = a0;
        sA[(lane16 * 4 + 1) * 66 + lr] = a1;
        sA[(lane16 * 4 + 2) * 66 + lr] = a2;
        sA[(lane16 * 4 + 3) * 66 + lr] = a3;
    }
    __syncthreads();

    // ---- Phase 2: 64x64 GEMM (f32x2), bias, store ------------------------
    const int rt = tid >> 4;
    const int ct = tid & 15;

    unsigned long long accq[2][4];
    #pragma unroll
    for (int rp = 0; rp < 2; rp++)
        #pragma unroll
        for (int j = 0; j < 4; j++)
            accq[rp][j] = 0ULL;

    #pragma unroll
    for (int k = 0; k < 64; k++) {
        const unsigned long long a01 =
            *reinterpret_cast<const unsigned long long*>(&sA[k * 66 + rt * 4]);
        const unsigned long long a23 =
            *reinterpret_cast<const unsigned long long*>(&sA[k * 66 + rt * 4 + 2]);
        const float4 w = *reinterpret_cast<const float4*>(&sW[k * 64 + ct * 4]);

        unsigned long long wx, wy, wz, ww;
        PACK2(wx, w.x); PACK2(wy, w.y); PACK2(wz, w.z); PACK2(ww, w.w);

        FMA2(accq[0][0], a01, wx); FMA2(accq[0][1], a01, wy);
        FMA2(accq[0][2], a01, wz); FMA2(accq[0][3], a01, ww);
        FMA2(accq[1][0], a23, wx); FMA2(accq[1][1], a23, wy);
        FMA2(accq[1][2], a23, wz); FMA2(accq[1][3], a23, ww);
    }

    float res[4][4];
    #pragma unroll
    for (int rp = 0; rp < 2; rp++)
        #pragma unroll
        for (int j = 0; j < 4; j++) {
            float lo, hi;
            UNPACK2(lo, hi, accq[rp][j]);
            res[rp * 2 + 0][j] = lo;
            res[rp * 2 + 1][j] = hi;
        }

    const float4 b = *reinterpret_cast<const float4*>(&bias[ct * 4]);

    #pragma unroll
    for (int i = 0; i < 4; i++) {
        int row = row0 + rt * 4 + i;
        if (row < E) {
            float4 v;
            v.x = res[i][0] + b.x;
            v.y = res[i][1] + b.y;
            v.z = res[i][2] + b.z;
            v.w = res[i][3] + b.w;
            *reinterpret_cast<float4*>(&out[row * 64 + ct * 4]) = v;
        }
    }
}

// ---------------------------------------------------------------------------
extern "C" void kernel_launch(void* const* d_in, const int* in_sizes, int n_in,
                              void* d_out, int out_size)
{
    const float* feat = (const float*)d_in[0];   // [E, 64] f32
    const int*   nbr  = (const int*)d_in[1];     // [P, 2]  i32
    const float* W    = (const float*)d_in[2];   // [64, 64] f32
    const float* bias = (const float*)d_in[3];   // [64] f32
    float* out = (float*)d_out;                  // [E, 64] f32

    const int E = in_sizes[0] / 64;
    const int P = in_sizes[1] / 2;

    const int P2    = (P + 1) / 2;
    const int blkP2 = (P2 + 255) / 256;
    const int NB    = (E + 1023) / 1024;         // <= 512

    // zero counts via async memset (graph-capturable, no alloc)
    void* counts_ptr = nullptr;
    cudaGetSymbolAddress(&counts_ptr, g_counts);
    cudaMemsetAsync(counts_ptr, 0, (size_t)E * sizeof(int), 0);

    // fp16 staging of the feature table
    const int n4 = E * 16;                       // float4 count
    convert_kernel<<<(n4 + 255) / 256, 256>>>((const float4*)feat, n4);

    hist_kernel<<<blkP2, 256>>>((const int4*)nbr, P2, P);
    scan_partial_kernel<<<NB, 256>>>(E);
    scan_blocksums_kernel<<<1, 512>>>(NB);
    scan_final_kernel<<<NB, 256>>>(E);
    sort_scatter_kernel<<<blkP2, 256>>>((const int4*)nbr, P2, P);

    const int blkA = (E + 63) / 64;
    agg_gemm_kernel<<<blkA, 256>>>(W, bias, out, E);
}

// round 9
// speedup vs baseline: 1.1912x; 1.1044x over previous
#include <cuda_runtime.h>
#include <cuda_fp16.h>

// E=500000, P=4000000, D=U=64.
__device__ int g_counts[500032];      // per-dst neighbor count
__device__ int g_offsets[500032];     // exclusive prefix of counts
__device__ int g_cursor[500032];      // scatter cursors
__device__ int g_src_sorted[4000000]; // src ids grouped by dst
__device__ int g_blockSums[512];
__device__ int g_blockOffs[512];
__device__ __half g_feat_h[500000 * 64];  // fp16 staged feature table (64 MB)

// f32x2 helpers (sm_103a packed fp32 pipe, PTX-only)
#define FMA2(d, a, b) \
    asm("fma.rn.f32x2 %0, %1, %2, %0;" : "+l"(d) : "l"(a), "l"(b))
#define PACK2(p, x) \
    asm("mov.b64 %0, {%1, %1};" : "=l"(p) : "f"(x))
#define UNPACK2(lo, hi, p) \
    asm("mov.b64 {%0, %1}, %2;" : "=f"(lo), "=f"(hi) : "l"(p))

// ---------------------------------------------------------------------------
// Combined prep kernel: blocks [0, nConv) stream-convert feat -> fp16;
// blocks [nConv, nConv+nHist) histogram dst ids. Independent work fused into
// one launch (fewer launches; also positions agg_gemm as the 6th kernel
// launch so the ncu -s 5 -c 1 capture lands on it).
// ---------------------------------------------------------------------------
__global__ void prep_kernel(const float4* __restrict__ feat4, int n4, int nConv,
                            const int4* __restrict__ nbr2, int P2, int P)
{
    if ((int)blockIdx.x < nConv) {
        int i = blockIdx.x * 256 + threadIdx.x;
        if (i >= n4) return;
        float4 v = __ldcs(&feat4[i]);
        __half2 h0 = __floats2half2_rn(v.x, v.y);
        __half2 h1 = __floats2half2_rn(v.z, v.w);
        uint2 u;
        u.x = *reinterpret_cast<unsigned int*>(&h0);
        u.y = *reinterpret_cast<unsigned int*>(&h1);
        reinterpret_cast<uint2*>(g_feat_h)[i] = u;
    } else {
        int q = (blockIdx.x - nConv) * 256 + threadIdx.x;
        if (q >= P2) return;
        int4 e = __ldcs(&nbr2[q]);     // {dst0, src0, dst1, src1}
        atomicAdd(&g_counts[e.x], 1);
        int p1 = q * 2 + 1;
        if (p1 < P) atomicAdd(&g_counts[e.z], 1);
    }
}

// ---------------------------------------------------------------------------
__global__ void scan_partial_kernel(int E)
{
    __shared__ int s[256];
    const int tid  = threadIdx.x;
    const int base = blockIdx.x * 1024 + tid * 4;
    int t = 0;
    #pragma unroll
    for (int j = 0; j < 4; j++) {
        int idx = base + j;
        if (idx < E) t += g_counts[idx];
    }
    s[tid] = t;
    __syncthreads();
    for (int o = 128; o > 0; o >>= 1) {
        if (tid < o) s[tid] += s[tid + o];
        __syncthreads();
    }
    if (tid == 0) g_blockSums[blockIdx.x] = s[0];
}

__global__ void scan_blocksums_kernel(int NB)
{
    __shared__ int s[512];
    const int tid = threadIdx.x;
    int v = (tid < NB) ? g_blockSums[tid] : 0;
    s[tid] = v;
    __syncthreads();
    for (int o = 1; o < 512; o <<= 1) {
        int t = (tid >= o) ? s[tid - o] : 0;
        __syncthreads();
        s[tid] += t;
        __syncthreads();
    }
    if (tid < NB) g_blockOffs[tid] = s[tid] - v;
}

__global__ void scan_final_kernel(int E)
{
    __shared__ int s[256];
    const int tid  = threadIdx.x;
    const int base = blockIdx.x * 1024 + tid * 4;

    int c[4];
    int tsum = 0;
    #pragma unroll
    for (int j = 0; j < 4; j++) {
        int idx = base + j;
        c[j] = (idx < E) ? g_counts[idx] : 0;
        tsum += c[j];
    }
    s[tid] = tsum;
    __syncthreads();
    for (int o = 1; o < 256; o <<= 1) {
        int t = (tid >= o) ? s[tid - o] : 0;
        __syncthreads();
        s[tid] += t;
        __syncthreads();
    }
    int run = g_blockOffs[blockIdx.x] + (s[tid] - tsum);
    #pragma unroll
    for (int j = 0; j < 4; j++) {
        int idx = base + j;
        if (idx < E) {
            g_offsets[idx] = run;
            g_cursor[idx]  = run;
        }
        run += c[j];
    }
}

__global__ void sort_scatter_kernel(const int4* __restrict__ nbr2, int P2, int P)
{
    int q = blockIdx.x * 256 + threadIdx.x;
    if (q >= P2) return;
    int4 e = __ldcs(&nbr2[q]);
    int pos0 = atomicAdd(&g_cursor[e.x], 1);
    g_src_sorted[pos0] = e.y;
    int p1 = q * 2 + 1;
    if (p1 < P) {
        int pos1 = atomicAdd(&g_cursor[e.z], 1);
        g_src_sorted[pos1] = e.w;
    }
}

// ---------------------------------------------------------------------------
// Fused aggregate + GEMM.
// Phase 1 gather: half-warp team per dst row, fp16 table, PADDED MLP-8
// batches: every row does ceil(cnt/8) full batches; lanes past the end clamp
// the index to the last valid slot (load always issued) and predicate off
// the accumulate. No serial tail -> ALL gather work runs at MLP-8.
// Phase 2: 64x64 f32x2 GEMM + bias (fp32).
// ---------------------------------------------------------------------------
__global__ void __launch_bounds__(256) agg_gemm_kernel(
    const float* __restrict__ W,      // [64, 64]
    const float* __restrict__ bias,   // [64]
    float* __restrict__ out,          // [E, 64]
    int E)
{
    __shared__ float sW[64 * 64];     // sW[k*64 + u]
    __shared__ float sA[64 * 66];     // sA[k*66 + r] (transposed, pad 66)

    const int tid  = threadIdx.x;
    const int row0 = blockIdx.x * 64;

    #pragma unroll
    for (int i = tid; i < 64 * 64; i += 256)
        sW[i] = W[i];

    // ---- Phase 1: gather + register accumulation -------------------------
    const int lane16 = tid & 15;          // column segment (4 halves = 8B)
    const int tteam  = tid >> 4;          // 0..15
    const uint2* __restrict__ fh =
        reinterpret_cast<const uint2*>(g_feat_h) + lane16;  // row stride 16

    #pragma unroll
    for (int rr = 0; rr < 4; rr++) {
        const int lr = rr * 16 + tteam;   // local row 0..63
        const int r  = row0 + lr;

        float a0 = 0.f, a1 = 0.f, a2 = 0.f, a3 = 0.f;
        if (r < E) {
            const int start = g_offsets[r];
            const int cnt   = g_counts[r];
            if (cnt > 0) {
                const int last  = start + cnt - 1;
                for (int i = start; i <= last; i += 8) {
                    int s_[8];
                    #pragma unroll
                    for (int j = 0; j < 8; j++) {
                        int idx = i + j;
                        s_[j] = __ldcs(&g_src_sorted[idx <= last ? idx : last]);
                    }
                    uint2 v[8];
                    #pragma unroll
                    for (int j = 0; j < 8; j++)
                        v[j] = fh[(long)s_[j] * 16];
                    #pragma unroll
                    for (int j = 0; j < 8; j++) {
                        if (i + j <= last) {
                            float2 f0 = __half22float2(*reinterpret_cast<__half2*>(&v[j].x));
                            float2 f1 = __half22float2(*reinterpret_cast<__half2*>(&v[j].y));
                            a0 += f0.x; a1 += f0.y; a2 += f1.x; a3 += f1.y;
                        }
                    }
                }
            }
        }
        sA[(lane16 * 4 + 0) * 66 + lr] = a0;
        sA[(lane16 * 4 + 1) * 66 + lr] = a1;
        sA[(lane16 * 4 + 2) * 66 + lr] = a2;
        sA[(lane16 * 4 + 3) * 66 + lr] = a3;
    }
    __syncthreads();

    // ---- Phase 2: 64x64 GEMM (f32x2), bias, store ------------------------
    const int rt = tid >> 4;
    const int ct = tid & 15;

    unsigned long long accq[2][4];
    #pragma unroll
    for (int rp = 0; rp < 2; rp++)
        #pragma unroll
        for (int j = 0; j < 4; j++)
            accq[rp][j] = 0ULL;

    #pragma unroll
    for (int k = 0; k < 64; k++) {
        const unsigned long long a01 =
            *reinterpret_cast<const unsigned long long*>(&sA[k * 66 + rt * 4]);
        const unsigned long long a23 =
            *reinterpret_cast<const unsigned long long*>(&sA[k * 66 + rt * 4 + 2]);
        const float4 w = *reinterpret_cast<const float4*>(&sW[k * 64 + ct * 4]);

        unsigned long long wx, wy, wz, ww;
        PACK2(wx, w.x); PACK2(wy, w.y); PACK2(wz, w.z); PACK2(ww, w.w);

        FMA2(accq[0][0], a01, wx); FMA2(accq[0][1], a01, wy);
        FMA2(accq[0][2], a01, wz); FMA2(accq[0][3], a01, ww);
        FMA2(accq[1][0], a23, wx); FMA2(accq[1][1], a23, wy);
        FMA2(accq[1][2], a23, wz); FMA2(accq[1][3], a23, ww);
    }

    float res[4][4];
    #pragma unroll
    for (int rp = 0; rp < 2; rp++)
        #pragma unroll
        for (int j = 0; j < 4; j++) {
            float lo, hi;
            UNPACK2(lo, hi, accq[rp][j]);
            res[rp * 2 + 0][j] = lo;
            res[rp * 2 + 1][j] = hi;
        }

    const float4 b = *reinterpret_cast<const float4*>(&bias[ct * 4]);

    #pragma unroll
    for (int i = 0; i < 4; i++) {
        int row = row0 + rt * 4 + i;
        if (row < E) {
            float4 v;
            v.x = res[i][0] + b.x;
            v.y = res[i][1] + b.y;
            v.z = res[i][2] + b.z;
            v.w = res[i][3] + b.w;
            *reinterpret_cast<float4*>(&out[row * 64 + ct * 4]) = v;
        }
    }
}

// ---------------------------------------------------------------------------
extern "C" void kernel_launch(void* const* d_in, const int* in_sizes, int n_in,
                              void* d_out, int out_size)
{
    const float* feat = (const float*)d_in[0];   // [E, 64] f32
    const int*   nbr  = (const int*)d_in[1];     // [P, 2]  i32
    const float* W    = (const float*)d_in[2];   // [64, 64] f32
    const float* bias = (const float*)d_in[3];   // [64] f32
    float* out = (float*)d_out;                  // [E, 64] f32

    const int E = in_sizes[0] / 64;
    const int P = in_sizes[1] / 2;

    const int P2    = (P + 1) / 2;
    const int blkP2 = (P2 + 255) / 256;
    const int NB    = (E + 1023) / 1024;         // <= 512
    const int n4    = E * 16;                    // float4 count for convert
    const int nConv = (n4 + 255) / 256;

    // zero counts via async memset (graph-capturable, no alloc)
    void* counts_ptr = nullptr;
    cudaGetSymbolAddress(&counts_ptr, g_counts);
    cudaMemsetAsync(counts_ptr, 0, (size_t)E * sizeof(int), 0);

    // fused fp16 staging + histogram (launch #1)
    prep_kernel<<<nConv + blkP2, 256>>>((const float4*)feat, n4, nConv,
                                        (const int4*)nbr, P2, P);

    scan_partial_kernel<<<NB, 256>>>(E);       // #2
    scan_blocksums_kernel<<<1, 512>>>(NB);     // #3
    scan_final_kernel<<<NB, 256>>>(E);         // #4
    sort_scatter_kernel<<<blkP2, 256>>>((const int4*)nbr, P2, P);  // #5

    const int blkA = (E + 63) / 64;
    agg_gemm_kernel<<<blkA, 256>>>(W, bias, out, E);               // #6
}